// round 12
// baseline (speedup 1.0000x reference)
#include <cuda_runtime.h>
#include <cuda_fp16.h>
#include <math.h>

#define NUM_ENT 40000
#define NUM_EMB 24
#define NUM_OPS 12
#define DIM     128
#define HID     128
#define BATCH   128
#define NNZ     300000
#define RANKS   3
#define STEPS   3
#define ETOT    (NUM_OPS * NNZ)
#define G4      (4 * HID)
#define ROWF    (RANKS * BATCH)     // 384 floats per entity row
#define ROW4    (ROWF / 4)
#define ROWH2   (ROWF / 4)          // 96 uint2 (fp16 rows)
#define NWORDS  (NUM_ENT / 16)
#define NPART   200
#define NKEYS   (NUM_ENT * 16)      // (dst,op) buckets, padded 12->16

// role split constants
#define LSTM_BLOCKS  (RANKS * 2 * NUM_EMB)          // 144
#define HIST_BLOCKS  ((ETOT / 4 + 255) / 256)       // 3516
#define OFFS_BLOCKS  ((NUM_ENT + 383) / 384)        // 105
#define SCAN_CH      40                              // rows per scan thread (1024*40 >= 40000)

// ---------------- scratch ----------------
__device__ float        g_memF[(size_t)NUM_ENT * ROWF];
__device__ uint2        g_memH1[(size_t)NUM_ENT * ROWH2];
__device__ uint2        g_memH2[(size_t)NUM_ENT * ROWH2];
__device__ int          g_hist12[NKEYS];
__device__ int          g_seg[NKEYS + 16];          // per-(dst,op) segment starts; [dst*16+12] = row end
__device__ int          g_rowptr[NUM_ENT + 1];
__device__ int          g_rank[ETOT];
__device__ int2         g_edge[ETOT];               // {src | op<<18, bits(val)}
__device__ unsigned int g_bitsA[NWORDS];
__device__ unsigned int g_bitsB[NWORDS];
__device__ float        g_hseq[RANKS * 2 * STEPS * NUM_EMB * HID];
__device__ float        g_attn24[RANKS * STEPS * 13 * NUM_EMB];
__device__ float        g_part[NPART * ROWF];
__device__ float        g_inv[ROWF];

__device__ __forceinline__ float warp_sum(float p) {
    p += __shfl_xor_sync(0xffffffffu, p, 16);
    p += __shfl_xor_sync(0xffffffffu, p, 8);
    p += __shfl_xor_sync(0xffffffffu, p, 4);
    p += __shfl_xor_sync(0xffffffffu, p, 2);
    p += __shfl_xor_sync(0xffffffffu, p, 1);
    return p;
}

// ---------------- K0: zero hist + flags ----------------
__global__ void k_zero() {
    int i = blockIdx.x * blockDim.x + threadIdx.x;
    if (i < NKEYS) g_hist12[i] = 0;
    if (i < NWORDS) g_bitsA[i] = 0;
}

// ---------------- K1: LSTM (blocks 0..143) + histogram w/ rank capture ----------------
__global__ void k_hist_lstm(const int4* __restrict__ edge_dst4,
                            const float* __restrict__ emb,
                            const float* __restrict__ Wih_f, const float* __restrict__ Whh_f,
                            const float* __restrict__ bih_f, const float* __restrict__ bhh_f,
                            const float* __restrict__ Wih_b, const float* __restrict__ Whh_b,
                            const float* __restrict__ bih_b, const float* __restrict__ bhh_b)
{
    __shared__ __align__(16) float sq[DIM];
    __shared__ __align__(16) float sh[HID];
    __shared__ float sc[HID];
    __shared__ float sz[G4];
    __shared__ float sxw[G4];

    int tid = threadIdx.x;
    if (blockIdx.x >= LSTM_BLOCKS) {
        // ---- histogram role ----
        int i = (blockIdx.x - LSTM_BLOCKS) * 256 + tid;
        if (i < ETOT / 4) {
            int4 d = edge_dst4[i];
            int op = (i * 4) / NNZ;
            int4 rk;
            rk.x = atomicAdd(&g_hist12[d.x * 16 + op], 1);
            rk.y = atomicAdd(&g_hist12[d.y * 16 + op], 1);
            rk.z = atomicAdd(&g_hist12[d.z * 16 + op], 1);
            rk.w = atomicAdd(&g_hist12[d.w * 16 + op], 1);
            ((int4*)g_rank)[i] = rk;
        }
        return;
    }

    // ---- LSTM role (blocks 0..143) ----
    int bb  = blockIdx.x % NUM_EMB;
    int dir = (blockIdx.x / NUM_EMB) % 2;
    int r   = blockIdx.x / (2 * NUM_EMB);
    const float* Wih = (dir ? Wih_b : Wih_f) + r * G4 * DIM;
    const float* Whh = (dir ? Whh_b : Whh_f) + r * G4 * HID;
    const float* bih = (dir ? bih_b : bih_f) + r * G4;
    const float* bhh = (dir ? bhh_b : bhh_f) + r * G4;

    int lane = tid & 31;
    int warp = tid >> 5;

    if (tid < DIM) {
        sq[tid] = emb[bb * DIM + tid];
        sh[tid] = 0.f;
        sc[tid] = 0.f;
    }
    __syncthreads();

    {
        float4 q4 = ((const float4*)sq)[lane];
        const float4* W4 = (const float4*)Wih;
        for (int o = 0; o < 64; o++) {
            int g = warp * 64 + o;
            float4 w = W4[g * 32 + lane];
            float p = w.x * q4.x + w.y * q4.y + w.z * q4.z + w.w * q4.w;
            p = warp_sum(p);
            if (lane == 0) sxw[g] = p + bih[g] + bhh[g];
        }
    }
    __syncthreads();

    for (int t = 0; t < STEPS; t++) {
        if (t == 0) {
            for (int g = tid; g < G4; g += 256) sz[g] = sxw[g];
        } else {
            float4 h4 = ((const float4*)sh)[lane];
            const float4* W4 = (const float4*)Whh;
            for (int o = 0; o < 64; o++) {
                int g = warp * 64 + o;
                float4 w = W4[g * 32 + lane];
                float p = w.x * h4.x + w.y * h4.y + w.z * h4.z + w.w * h4.w;
                p = warp_sum(p);
                if (lane == 0) sz[g] = sxw[g] + p;
            }
        }
        __syncthreads();
        if (tid < HID) {
            float zi = sz[tid], zf = sz[tid + HID], zg = sz[tid + 2 * HID], zo = sz[tid + 3 * HID];
            float ig = 1.f / (1.f + expf(-zi));
            float fg = 1.f / (1.f + expf(-zf));
            float gg = tanhf(zg);
            float og = 1.f / (1.f + expf(-zo));
            float c = fg * sc[tid] + ig * gg;
            float h = og * tanhf(c);
            sc[tid] = c;
            sh[tid] = h;
            g_hseq[(((r * 2 + dir) * STEPS + t) * NUM_EMB + bb) * HID + tid] = h;
        }
        __syncthreads();
    }
}

// ---------------- K2: attn (9 blocks, 256 threads) ----------------
__global__ void k_attn(const float* __restrict__ W0, const float* __restrict__ b0p) {
    __shared__ float sW[256 * 13];
    int tid = threadIdx.x;
    int r = blockIdx.x / STEPS;
    int t = blockIdx.x % STEPS;
    for (int i = tid; i < 256 * 13; i += 256) sW[i] = W0[i];
    __syncthreads();
    if (tid >= NUM_EMB) return;
    int q = tid;
    const float* hf = &g_hseq[(((r * 2 + 0) * STEPS + t) * NUM_EMB + q) * HID];
    const float* hb = &g_hseq[(((r * 2 + 1) * STEPS + (STEPS - 1 - t)) * NUM_EMB + q) * HID];
    float l[13];
    #pragma unroll
    for (int k = 0; k < 13; k++) l[k] = b0p[k];
    for (int d = 0; d < HID; d++) {
        float hv = hf[d];
        #pragma unroll
        for (int k = 0; k < 13; k++) l[k] += hv * sW[d * 13 + k];
    }
    for (int d = 0; d < HID; d++) {
        float hv = hb[d];
        #pragma unroll
        for (int k = 0; k < 13; k++) l[k] += hv * sW[(HID + d) * 13 + k];
    }
    float m = l[0];
    #pragma unroll
    for (int k = 1; k < 13; k++) m = fmaxf(m, l[k]);
    float s = 0.f;
    #pragma unroll
    for (int k = 0; k < 13; k++) { l[k] = expf(l[k] - m); s += l[k]; }
    float inv = 1.f / s;
    #pragma unroll
    for (int k = 0; k < 13; k++)
        g_attn24[((r * STEPS + t) * 13 + k) * NUM_EMB + q] = l[k] * inv;
}

// ---------------- K3: fused rowsum + shuffle scan (1 block, 1024 threads) ----------------
__global__ void k_scan() {
    __shared__ int swarp[32];
    int tid  = threadIdx.x;
    int lane = tid & 31;
    int warp = tid >> 5;

    int start = tid * SCAN_CH;
    int cnt[SCAN_CH];
    int s = 0;
    #pragma unroll
    for (int k = 0; k < SCAN_CH; k++) {
        int idx = start + k;
        int c = 0;
        if (idx < NUM_ENT) {
            const int4* h4 = (const int4*)&g_hist12[idx * 16];
            int4 a = h4[0], b = h4[1], cc = h4[2];
            c = a.x + a.y + a.z + a.w + b.x + b.y + b.z + b.w + cc.x + cc.y + cc.z + cc.w;
        }
        cnt[k] = c;
        s += c;
    }

    // inclusive warp scan of per-thread sums
    int inc = s;
    #pragma unroll
    for (int d = 1; d < 32; d <<= 1) {
        int n = __shfl_up_sync(0xffffffffu, inc, d);
        if (lane >= d) inc += n;
    }
    if (lane == 31) swarp[warp] = inc;
    __syncthreads();
    if (warp == 0) {
        int v = swarp[lane];
        #pragma unroll
        for (int d = 1; d < 32; d <<= 1) {
            int n = __shfl_up_sync(0xffffffffu, v, d);
            if (lane >= d) v += n;
        }
        swarp[lane] = v;
    }
    __syncthreads();

    int run = (inc - s) + (warp ? swarp[warp - 1] : 0);   // exclusive prefix
    #pragma unroll
    for (int k = 0; k < SCAN_CH; k++) {
        int idx = start + k;
        if (idx < NUM_ENT) g_rowptr[idx] = run;
        run += cnt[k];
    }
    if (tid == 0) g_rowptr[NUM_ENT] = swarp[31];
}

// ---------------- K4: per-(dst,op) segment offsets ----------------
__global__ void k_offsets(void) {
    int dst = blockIdx.x * 384 + threadIdx.x;
    if (dst < NUM_ENT) {
        int run = g_rowptr[dst];
        #pragma unroll
        for (int op = 0; op < NUM_OPS; op++) {
            g_seg[dst * 16 + op] = run;
            run += g_hist12[dst * 16 + op];
        }
        g_seg[dst * 16 + 12] = run;
    }
}

// ---------------- fused init: zero head rows, then set ones (1 block, ordered) ----------------
__global__ void k_init(const int* __restrict__ heads) {
    __shared__ int srow[BATCH];
    int tid = threadIdx.x;     // 384
    if (tid < BATCH) srow[tid] = heads[tid];
    __syncthreads();
    for (int b = 0; b < BATCH; b++)
        g_memF[(size_t)srow[b] * ROWF + tid] = 0.f;
    __syncthreads();
    if (tid < BATCH) {
        int row = srow[tid];
        #pragma unroll
        for (int r = 0; r < RANKS; r++)
            g_memF[(size_t)row * ROWF + r * BATCH + tid] = 1.f;
        atomicOr(&g_bitsA[row >> 4], 1u << (row & 15));
    }
}

// ---------------- K5: scatter (atomic-free) ----------------
__global__ void k_scatter(const int4* __restrict__ src4,
                          const int4* __restrict__ dst4,
                          const float4* __restrict__ val4) {
    int i = blockIdx.x * blockDim.x + threadIdx.x;
    if (i >= ETOT / 4) return;
    int4   s = src4[i];
    int4   d = dst4[i];
    float4 v = val4[i];
    int4   rk = ((const int4*)g_rank)[i];
    int op = (i * 4) / NNZ;
    int tag = op << 18;
    g_edge[g_seg[d.x * 16 + op] + rk.x] = make_int2(s.x | tag, __float_as_int(v.x));
    g_edge[g_seg[d.y * 16 + op] + rk.y] = make_int2(s.y | tag, __float_as_int(v.y));
    g_edge[g_seg[d.z * 16 + op] + rk.z] = make_int2(s.z | tag, __float_as_int(v.z));
    g_edge[g_seg[d.w * 16 + op] + rk.w] = make_int2(s.w | tag, __float_as_int(v.w));
}

// ---------------- sparse applies (steps 0,1): ballot-compacted ----------------
template<int STEP>
__global__ void apply_kernel(const int* __restrict__ queries) {
    constexpr bool IN_HALF     = (STEP >= 1);
    constexpr bool WRITE_FLAGS = (STEP < 1);

    __shared__ __align__(16) float4 sAttn4[RANKS * 13 * 32];
    __shared__ unsigned int sbits[NWORDS];
    __shared__ unsigned char sAny[16];

    const unsigned int* bitsIn  = (STEP == 1) ? g_bitsB : g_bitsA;

    int tid = threadIdx.x;
    for (int i = tid; i < NWORDS; i += 512) sbits[i] = bitsIn[i];
    float* sAttnF = (float*)sAttn4;
    for (int i = tid; i < RANKS * 13 * BATCH; i += 512) {
        int rk = i >> 7;
        int b  = i & 127;
        int r  = rk / 13, k = rk - r * 13;
        sAttnF[i] = g_attn24[((r * STEPS + STEP) * 13 + k) * NUM_EMB + queries[b]];
    }
    __syncthreads();

    int lane = tid & 31;
    int warp = tid >> 5;
    int j = blockIdx.x * 16 + warp;

    int rs = g_rowptr[j];
    int re = g_rowptr[j + 1];

    float4 acc[RANKS];
    #pragma unroll
    for (int r = 0; r < RANKS; r++) acc[r] = make_float4(0.f, 0.f, 0.f, 0.f);

    const uint2* memH = (const uint2*)g_memH1;
    unsigned int any = (sbits[j >> 4] >> (j & 15)) & 1u;
    if (any) {
        #pragma unroll
        for (int r = 0; r < RANKS; r++) {
            float4 a = sAttn4[(r * 13 + 12) * 32 + lane];
            float4 m;
            if constexpr (IN_HALF) {
                uint2 u = memH[(size_t)j * ROWH2 + r * 32 + lane];
                float2 f0 = __half22float2(*reinterpret_cast<__half2*>(&u.x));
                float2 f1 = __half22float2(*reinterpret_cast<__half2*>(&u.y));
                m = make_float4(f0.x, f0.y, f1.x, f1.y);
            } else {
                m = ((const float4*)g_memF)[(size_t)j * ROW4 + r * 32 + lane];
            }
            acc[r].x = a.x * m.x; acc[r].y = a.y * m.y;
            acc[r].z = a.z * m.z; acc[r].w = a.w * m.w;
        }
    }

    for (int e0 = rs; e0 < re; e0 += 32) {
        int e = e0 + lane;
        int meta = 0; float val = 0.f;
        bool act = false;
        if (e < re) {
            int2 ev = g_edge[e];
            meta = ev.x;
            val  = __int_as_float(ev.y);
            int s = meta & 0x3FFFF;
            act = (sbits[s >> 4] >> (s & 15)) & 1u;
        }
        unsigned int mask = __ballot_sync(0xffffffffu, act);
        any |= mask;
        while (mask) {
            int k = __ffs(mask) - 1;
            mask &= mask - 1;
            int   mk = __shfl_sync(0xffffffffu, meta, k);
            float vk = __shfl_sync(0xffffffffu, val,  k);
            int srck = mk & 0x3FFFF;
            int opk  = mk >> 18;
            if constexpr (IN_HALF) {
                const uint2* mrow = memH + (size_t)srck * ROWH2 + lane;
                uint2 u0 = mrow[0];
                uint2 u1 = mrow[32];
                uint2 u2 = mrow[64];
                const uint2 uu[3] = {u0, u1, u2};
                #pragma unroll
                for (int r = 0; r < RANKS; r++) {
                    float2 f0 = __half22float2(*reinterpret_cast<const __half2*>(&uu[r].x));
                    float2 f1 = __half22float2(*reinterpret_cast<const __half2*>(&uu[r].y));
                    float4 a = sAttn4[(r * 13 + opk) * 32 + lane];
                    acc[r].x = fmaf(vk * a.x, f0.x, acc[r].x);
                    acc[r].y = fmaf(vk * a.y, f0.y, acc[r].y);
                    acc[r].z = fmaf(vk * a.z, f1.x, acc[r].z);
                    acc[r].w = fmaf(vk * a.w, f1.y, acc[r].w);
                }
            } else {
                const float4* mrow = ((const float4*)g_memF) + (size_t)srck * ROW4 + lane;
                float4 m0 = mrow[0];
                float4 m1 = mrow[32];
                float4 m2 = mrow[64];
                const float4 mm[3] = {m0, m1, m2};
                #pragma unroll
                for (int r = 0; r < RANKS; r++) {
                    float4 a = sAttn4[(r * 13 + opk) * 32 + lane];
                    acc[r].x = fmaf(vk * a.x, mm[r].x, acc[r].x);
                    acc[r].y = fmaf(vk * a.y, mm[r].y, acc[r].y);
                    acc[r].z = fmaf(vk * a.z, mm[r].z, acc[r].z);
                    acc[r].w = fmaf(vk * a.w, mm[r].w, acc[r].w);
                }
            }
        }
    }

    {
        uint2* orow = ((uint2*)(STEP == 0 ? g_memH1 : g_memH2)) + (size_t)j * ROWH2;
        #pragma unroll
        for (int r = 0; r < RANKS; r++) {
            __half2 h0 = __floats2half2_rn(acc[r].x, acc[r].y);
            __half2 h1 = __floats2half2_rn(acc[r].z, acc[r].w);
            uint2 o;
            o.x = *reinterpret_cast<unsigned int*>(&h0);
            o.y = *reinterpret_cast<unsigned int*>(&h1);
            orow[r * 32 + lane] = o;
        }
    }

    if constexpr (WRITE_FLAGS) {
        if (lane == 0) sAny[warp] = (unsigned char)(any ? 1 : 0);
        __syncthreads();
        if (tid < 32) {
            unsigned int m = __ballot_sync(0xffffffffu, tid < 16 && sAny[tid]);
            if (tid == 0) g_bitsB[blockIdx.x] = m & 0xFFFFu;
        }
    }
}

// ---------------- dense apply t=2: op-segmented, two-level accumulation ----------------
__global__ void apply_dense_kernel(const int* __restrict__ queries) {
    __shared__ __align__(16) float4 sAttn4[RANKS * 13 * 32];

    int tid = threadIdx.x;
    float* sAttnF = (float*)sAttn4;
    for (int i = tid; i < RANKS * 13 * BATCH; i += 256) {
        int rk = i >> 7;
        int b  = i & 127;
        int r  = rk / 13, k = rk - r * 13;
        sAttnF[i] = g_attn24[((r * STEPS + 2) * 13 + k) * NUM_EMB + queries[b]];
    }
    __syncthreads();

    int lane = tid & 31;
    int warp = tid >> 5;
    int j = blockIdx.x * 8 + warp;

    float4 acc[RANKS];
    const uint2* memH = (const uint2*)g_memH2;

    {   // identity operator (k=12)
        #pragma unroll
        for (int r = 0; r < RANKS; r++) {
            float4 a = sAttn4[(r * 13 + 12) * 32 + lane];
            uint2 u = memH[(size_t)j * ROWH2 + r * 32 + lane];
            float2 f0 = __half22float2(*reinterpret_cast<__half2*>(&u.x));
            float2 f1 = __half22float2(*reinterpret_cast<__half2*>(&u.y));
            acc[r].x = a.x * f0.x; acc[r].y = a.y * f0.y;
            acc[r].z = a.z * f1.x; acc[r].w = a.w * f1.y;
        }
    }

    int segend = g_seg[j * 16 + 0];
    #pragma unroll
    for (int op = 0; op < NUM_OPS; op++) {
        int s = segend;
        segend = g_seg[j * 16 + op + 1];
        float4 T[RANKS];
        #pragma unroll
        for (int r = 0; r < RANKS; r++) T[r] = make_float4(0.f, 0.f, 0.f, 0.f);

        #pragma unroll 4
        for (int e = s; e < segend; e++) {
            int2 ev = g_edge[e];
            int   src = ev.x & 0x3FFFF;
            float vk  = __int_as_float(ev.y);
            const uint2* mrow = memH + (size_t)src * ROWH2 + lane;
            uint2 u0 = mrow[0];
            uint2 u1 = mrow[32];
            uint2 u2 = mrow[64];
            {
                float2 f0 = __half22float2(*reinterpret_cast<const __half2*>(&u0.x));
                float2 f1 = __half22float2(*reinterpret_cast<const __half2*>(&u0.y));
                T[0].x = fmaf(vk, f0.x, T[0].x);
                T[0].y = fmaf(vk, f0.y, T[0].y);
                T[0].z = fmaf(vk, f1.x, T[0].z);
                T[0].w = fmaf(vk, f1.y, T[0].w);
            }
            {
                float2 f0 = __half22float2(*reinterpret_cast<const __half2*>(&u1.x));
                float2 f1 = __half22float2(*reinterpret_cast<const __half2*>(&u1.y));
                T[1].x = fmaf(vk, f0.x, T[1].x);
                T[1].y = fmaf(vk, f0.y, T[1].y);
                T[1].z = fmaf(vk, f1.x, T[1].z);
                T[1].w = fmaf(vk, f1.y, T[1].w);
            }
            {
                float2 f0 = __half22float2(*reinterpret_cast<const __half2*>(&u2.x));
                float2 f1 = __half22float2(*reinterpret_cast<const __half2*>(&u2.y));
                T[2].x = fmaf(vk, f0.x, T[2].x);
                T[2].y = fmaf(vk, f0.y, T[2].y);
                T[2].z = fmaf(vk, f1.x, T[2].z);
                T[2].w = fmaf(vk, f1.y, T[2].w);
            }
        }

        #pragma unroll
        for (int r = 0; r < RANKS; r++) {
            float4 a = sAttn4[(r * 13 + op) * 32 + lane];
            acc[r].x = fmaf(a.x, T[r].x, acc[r].x);
            acc[r].y = fmaf(a.y, T[r].y, acc[r].y);
            acc[r].z = fmaf(a.z, T[r].z, acc[r].z);
            acc[r].w = fmaf(a.w, T[r].w, acc[r].w);
        }
    }

    float4* orow = ((float4*)g_memF) + (size_t)j * ROW4;
    #pragma unroll
    for (int r = 0; r < RANKS; r++) orow[r * 32 + lane] = acc[r];
}

// ---------------- normalize + fused output ----------------
__global__ void partial_kernel() {
    int tid = threadIdx.x;
    int j0  = blockIdx.x * (NUM_ENT / NPART);
    float s = 0.f;
    for (int k = 0; k < NUM_ENT / NPART; k++)
        s += g_memF[(size_t)(j0 + k) * ROWF + tid];
    g_part[blockIdx.x * ROWF + tid] = s;
}
__global__ void norm_kernel() {
    int tid = threadIdx.x;
    float s = 0.f;
    for (int k = 0; k < NPART; k++) s += g_part[k * ROWF + tid];
    g_inv[tid] = 1.f / fmaxf(1e-20f, s);
}
__global__ void final_kernel(float* __restrict__ out) {
    __shared__ float tile[32][33];
    __shared__ float sinv[RANKS][32];
    int j0 = blockIdx.x * 32, b0 = blockIdx.y * 32;
    int x = threadIdx.x, y = threadIdx.y;
    if (y < RANKS) sinv[y][x] = g_inv[y * BATCH + b0 + x];
    __syncthreads();
    const float* row = &g_memF[(size_t)(j0 + y) * ROWF + b0 + x];
    float v = row[0] * sinv[0][x] + row[BATCH] * sinv[1][x] + row[2 * BATCH] * sinv[2][x];
    tile[y][x] = v;
    __syncthreads();
    out[(size_t)(b0 + y) * NUM_ENT + (j0 + x)] = tile[x][y];
}

// ---------------- launch ----------------
extern "C" void kernel_launch(void* const* d_in, const int* in_sizes, int n_in,
                              void* d_out, int out_size) {
    const int*   queries  = (const int*)d_in[0];
    const int*   heads    = (const int*)d_in[1];
    const int*   edge_src = (const int*)d_in[2];
    const int*   edge_dst = (const int*)d_in[3];
    const float* edge_val = (const float*)d_in[4];
    const float* emb      = (const float*)d_in[5];
    const float* Wih_f    = (const float*)d_in[6];
    const float* Whh_f    = (const float*)d_in[7];
    const float* bih_f    = (const float*)d_in[8];
    const float* bhh_f    = (const float*)d_in[9];
    const float* Wih_b    = (const float*)d_in[10];
    const float* Whh_b    = (const float*)d_in[11];
    const float* bih_b    = (const float*)d_in[12];
    const float* bhh_b    = (const float*)d_in[13];
    const float* W0       = (const float*)d_in[14];
    const float* b0       = (const float*)d_in[15];
    float* out = (float*)d_out;
    (void)in_sizes; (void)n_in; (void)out_size;

    // K0: zero hist + flags
    k_zero<<<(NKEYS + 255) / 256, 256>>>();
    // K1: LSTM (first 144 blocks) overlapped with (dst,op)-histogram + rank capture
    k_hist_lstm<<<LSTM_BLOCKS + HIST_BLOCKS, 256>>>((const int4*)edge_dst, emb,
                                                    Wih_f, Whh_f, bih_f, bhh_f,
                                                    Wih_b, Whh_b, bih_b, bhh_b);
    // K2: attention coefficients (tiny)
    k_attn<<<RANKS * STEPS, 256>>>(W0, b0);
    // K3: fused rowsum + shuffle scan
    k_scan<<<1, 1024>>>();
    // K4: per-(dst,op) segment offsets
    k_offsets<<<OFFS_BLOCKS, 384>>>();
    // fused init (zero head rows, then ones + flags; single block for ordering)
    k_init<<<1, ROWF>>>(heads);
    // K5: atomic-free scatter
    k_scatter<<<(ETOT / 4 + 255) / 256, 256>>>((const int4*)edge_src,
                                               (const int4*)edge_dst,
                                               (const float4*)edge_val);

    // applies: sparse (flags) -> sparse (flags) -> dense (op-segmented)
    apply_kernel<0><<<NUM_ENT / 16, 512>>>(queries);
    apply_kernel<1><<<NUM_ENT / 16, 512>>>(queries);
    apply_dense_kernel<<<NUM_ENT / 8, 256>>>(queries);

    // normalize per rank, sum ranks, transpose to (B, ENT)
    partial_kernel<<<NPART, ROWF>>>();
    norm_kernel<<<1, ROWF>>>();
    final_kernel<<<dim3(NUM_ENT / 32, BATCH / 32), dim3(32, 32)>>>(out);
}

// round 14
// speedup vs baseline: 1.0934x; 1.0934x over previous
#include <cuda_runtime.h>
#include <cuda_fp16.h>
#include <math.h>

#define NUM_ENT 40000
#define NUM_EMB 24
#define NUM_OPS 12
#define DIM     128
#define HID     128
#define BATCH   128
#define NNZ     300000
#define RANKS   3
#define STEPS   3
#define ETOT    (NUM_OPS * NNZ)
#define G4      (4 * HID)
#define ROWF    (RANKS * BATCH)     // 384 floats per entity row
#define ROW4    (ROWF / 4)
#define ROWH2   (ROWF / 4)          // 96 uint2 (fp16 rows)
#define NWORDS  (NUM_ENT / 16)
#define NPART   200
#define NKEYS   (NUM_ENT * 16)      // (dst,op) buckets, padded 12->16

// role split constants
#define LSTM_BLOCKS  (RANKS * 2 * NUM_EMB)          // 144
#define HIST_BLOCKS  ((ETOT / 4 + 255) / 256)       // 3516
#define ATTN_BLOCKS  (RANKS * STEPS)                // 9
#define RSUM_BLOCKS  ((NUM_ENT + 255) / 256)        // 157
#define OFFS_BLOCKS  ((NUM_ENT + 383) / 384)        // 105
#define SCAN_CH      40                              // rows per scan thread
#define RC_PAD       (1024 * SCAN_CH)                // 40960 (padded rowcnt)

// ---------------- scratch ----------------
__device__ float        g_memF[(size_t)NUM_ENT * ROWF];
__device__ uint2        g_memH1[(size_t)NUM_ENT * ROWH2];
__device__ uint2        g_memH2[(size_t)NUM_ENT * ROWH2];
__device__ int          g_hist12[NKEYS];
__device__ int          g_seg[NKEYS + 16];          // per-(dst,op) segment starts; [dst*16+12] = row end
__device__ int          g_rowcnt[RC_PAD];           // padded; tail zeroed
__device__ int          g_rowptr[NUM_ENT + 1];
__device__ int          g_rank[ETOT];
__device__ int2         g_edge[ETOT];               // {src | op<<18, bits(val)}
__device__ unsigned int g_bitsA[NWORDS];
__device__ unsigned int g_bitsB[NWORDS];
__device__ float        g_hseq[RANKS * 2 * STEPS * NUM_EMB * HID];
__device__ float        g_attn24[RANKS * STEPS * 13 * NUM_EMB];
__device__ float        g_part[NPART * ROWF];
__device__ float        g_inv[ROWF];

__device__ __forceinline__ float warp_sum(float p) {
    p += __shfl_xor_sync(0xffffffffu, p, 16);
    p += __shfl_xor_sync(0xffffffffu, p, 8);
    p += __shfl_xor_sync(0xffffffffu, p, 4);
    p += __shfl_xor_sync(0xffffffffu, p, 2);
    p += __shfl_xor_sync(0xffffffffu, p, 1);
    return p;
}

// ---------------- K0: zero hist + flags + rowcnt pad ----------------
__global__ void k_zero() {
    int i = blockIdx.x * blockDim.x + threadIdx.x;
    if (i < NKEYS) g_hist12[i] = 0;
    if (i < NWORDS) g_bitsA[i] = 0;
    if (i < RC_PAD) g_rowcnt[i] = 0;
}

// ---------------- K1: LSTM (blocks 0..143) + histogram w/ rank capture ----------------
__global__ void k_hist_lstm(const int4* __restrict__ edge_dst4,
                            const float* __restrict__ emb,
                            const float* __restrict__ Wih_f, const float* __restrict__ Whh_f,
                            const float* __restrict__ bih_f, const float* __restrict__ bhh_f,
                            const float* __restrict__ Wih_b, const float* __restrict__ Whh_b,
                            const float* __restrict__ bih_b, const float* __restrict__ bhh_b)
{
    __shared__ __align__(16) float sq[DIM];
    __shared__ __align__(16) float sh[HID];
    __shared__ float sc[HID];
    __shared__ float sz[G4];
    __shared__ float sxw[G4];

    int tid = threadIdx.x;
    if (blockIdx.x >= LSTM_BLOCKS) {
        // ---- histogram role ----
        int i = (blockIdx.x - LSTM_BLOCKS) * 256 + tid;
        if (i < ETOT / 4) {
            int4 d = edge_dst4[i];
            int op = (i * 4) / NNZ;
            int4 rk;
            rk.x = atomicAdd(&g_hist12[d.x * 16 + op], 1);
            rk.y = atomicAdd(&g_hist12[d.y * 16 + op], 1);
            rk.z = atomicAdd(&g_hist12[d.z * 16 + op], 1);
            rk.w = atomicAdd(&g_hist12[d.w * 16 + op], 1);
            ((int4*)g_rank)[i] = rk;
        }
        return;
    }

    // ---- LSTM role (blocks 0..143) ----
    int bb  = blockIdx.x % NUM_EMB;
    int dir = (blockIdx.x / NUM_EMB) % 2;
    int r   = blockIdx.x / (2 * NUM_EMB);
    const float* Wih = (dir ? Wih_b : Wih_f) + r * G4 * DIM;
    const float* Whh = (dir ? Whh_b : Whh_f) + r * G4 * HID;
    const float* bih = (dir ? bih_b : bih_f) + r * G4;
    const float* bhh = (dir ? bhh_b : bhh_f) + r * G4;

    int lane = tid & 31;
    int warp = tid >> 5;

    if (tid < DIM) {
        sq[tid] = emb[bb * DIM + tid];
        sh[tid] = 0.f;
        sc[tid] = 0.f;
    }
    __syncthreads();

    {
        float4 q4 = ((const float4*)sq)[lane];
        const float4* W4 = (const float4*)Wih;
        for (int o = 0; o < 64; o++) {
            int g = warp * 64 + o;
            float4 w = W4[g * 32 + lane];
            float p = w.x * q4.x + w.y * q4.y + w.z * q4.z + w.w * q4.w;
            p = warp_sum(p);
            if (lane == 0) sxw[g] = p + bih[g] + bhh[g];
        }
    }
    __syncthreads();

    for (int t = 0; t < STEPS; t++) {
        if (t == 0) {
            for (int g = tid; g < G4; g += 256) sz[g] = sxw[g];
        } else {
            float4 h4 = ((const float4*)sh)[lane];
            const float4* W4 = (const float4*)Whh;
            for (int o = 0; o < 64; o++) {
                int g = warp * 64 + o;
                float4 w = W4[g * 32 + lane];
                float p = w.x * h4.x + w.y * h4.y + w.z * h4.z + w.w * h4.w;
                p = warp_sum(p);
                if (lane == 0) sz[g] = sxw[g] + p;
            }
        }
        __syncthreads();
        if (tid < HID) {
            float zi = sz[tid], zf = sz[tid + HID], zg = sz[tid + 2 * HID], zo = sz[tid + 3 * HID];
            float ig = 1.f / (1.f + expf(-zi));
            float fg = 1.f / (1.f + expf(-zf));
            float gg = tanhf(zg);
            float og = 1.f / (1.f + expf(-zo));
            float c = fg * sc[tid] + ig * gg;
            float h = og * tanhf(c);
            sc[tid] = c;
            sh[tid] = h;
            g_hseq[(((r * 2 + dir) * STEPS + t) * NUM_EMB + bb) * HID + tid] = h;
        }
        __syncthreads();
    }
}

// ---------------- K2: attn (blocks 0..8) + parallel rowsum (blocks 9+) ----------------
__global__ void k_rowsum_attn(const float* __restrict__ W0, const float* __restrict__ b0p) {
    __shared__ float sW[256 * 13];
    int tid = threadIdx.x;
    if (blockIdx.x >= ATTN_BLOCKS) {
        int dst = (blockIdx.x - ATTN_BLOCKS) * 256 + tid;
        if (dst < NUM_ENT) {
            const int4* h4 = (const int4*)&g_hist12[dst * 16];
            int4 a = h4[0], b = h4[1], c = h4[2];
            g_rowcnt[dst] = a.x + a.y + a.z + a.w + b.x + b.y + b.z + b.w + c.x + c.y + c.z + c.w;
        }
        return;
    }
    int r = blockIdx.x / STEPS;
    int t = blockIdx.x % STEPS;
    for (int i = tid; i < 256 * 13; i += 256) sW[i] = W0[i];
    __syncthreads();
    if (tid >= NUM_EMB) return;
    int q = tid;
    const float* hf = &g_hseq[(((r * 2 + 0) * STEPS + t) * NUM_EMB + q) * HID];
    const float* hb = &g_hseq[(((r * 2 + 1) * STEPS + (STEPS - 1 - t)) * NUM_EMB + q) * HID];
    float l[13];
    #pragma unroll
    for (int k = 0; k < 13; k++) l[k] = b0p[k];
    for (int d = 0; d < HID; d++) {
        float hv = hf[d];
        #pragma unroll
        for (int k = 0; k < 13; k++) l[k] += hv * sW[d * 13 + k];
    }
    for (int d = 0; d < HID; d++) {
        float hv = hb[d];
        #pragma unroll
        for (int k = 0; k < 13; k++) l[k] += hv * sW[(HID + d) * 13 + k];
    }
    float m = l[0];
    #pragma unroll
    for (int k = 1; k < 13; k++) m = fmaxf(m, l[k]);
    float s = 0.f;
    #pragma unroll
    for (int k = 0; k < 13; k++) { l[k] = expf(l[k] - m); s += l[k]; }
    float inv = 1.f / s;
    #pragma unroll
    for (int k = 0; k < 13; k++)
        g_attn24[((r * STEPS + t) * 13 + k) * NUM_EMB + q] = l[k] * inv;
}

// ---------------- K3: shuffle scan over g_rowcnt (1 block, 1024 threads) ----------------
__global__ void k_scan() {
    __shared__ int swarp[32];
    int tid  = threadIdx.x;
    int lane = tid & 31;
    int warp = tid >> 5;

    int start = tid * SCAN_CH;
    int cnt[SCAN_CH];
    const int4* rc4 = (const int4*)&g_rowcnt[start];
    int s = 0;
    #pragma unroll
    for (int k = 0; k < SCAN_CH / 4; k++) {        // 10 independent int4 loads
        int4 c4 = rc4[k];
        cnt[k * 4 + 0] = c4.x;
        cnt[k * 4 + 1] = c4.y;
        cnt[k * 4 + 2] = c4.z;
        cnt[k * 4 + 3] = c4.w;
        s += c4.x + c4.y + c4.z + c4.w;
    }

    // inclusive warp scan of per-thread sums
    int inc = s;
    #pragma unroll
    for (int d = 1; d < 32; d <<= 1) {
        int n = __shfl_up_sync(0xffffffffu, inc, d);
        if (lane >= d) inc += n;
    }
    if (lane == 31) swarp[warp] = inc;
    __syncthreads();
    if (warp == 0) {
        int v = swarp[lane];
        #pragma unroll
        for (int d = 1; d < 32; d <<= 1) {
            int n = __shfl_up_sync(0xffffffffu, v, d);
            if (lane >= d) v += n;
        }
        swarp[lane] = v;
    }
    __syncthreads();

    int run = (inc - s) + (warp ? swarp[warp - 1] : 0);   // exclusive prefix
    #pragma unroll
    for (int k = 0; k < SCAN_CH; k++) {
        int idx = start + k;
        if (idx < NUM_ENT) g_rowptr[idx] = run;
        run += cnt[k];
    }
    if (tid == 0) g_rowptr[NUM_ENT] = swarp[31];
}

// ---------------- K4: per-(dst,op) segment offsets ----------------
__global__ void k_offsets(void) {
    int dst = blockIdx.x * 384 + threadIdx.x;
    if (dst < NUM_ENT) {
        int run = g_rowptr[dst];
        #pragma unroll
        for (int op = 0; op < NUM_OPS; op++) {
            g_seg[dst * 16 + op] = run;
            run += g_hist12[dst * 16 + op];
        }
        g_seg[dst * 16 + 12] = run;
    }
}

// ---------------- fused init: zero head rows, then set ones (1 block, ordered) ----------------
__global__ void k_init(const int* __restrict__ heads) {
    __shared__ int srow[BATCH];
    int tid = threadIdx.x;     // 384
    if (tid < BATCH) srow[tid] = heads[tid];
    __syncthreads();
    for (int b = 0; b < BATCH; b++)
        g_memF[(size_t)srow[b] * ROWF + tid] = 0.f;
    __syncthreads();
    if (tid < BATCH) {
        int row = srow[tid];
        #pragma unroll
        for (int r = 0; r < RANKS; r++)
            g_memF[(size_t)row * ROWF + r * BATCH + tid] = 1.f;
        atomicOr(&g_bitsA[row >> 4], 1u << (row & 15));
    }
}

// ---------------- K5: scatter (atomic-free) ----------------
__global__ void k_scatter(const int4* __restrict__ src4,
                          const int4* __restrict__ dst4,
                          const float4* __restrict__ val4) {
    int i = blockIdx.x * blockDim.x + threadIdx.x;
    if (i >= ETOT / 4) return;
    int4   s = src4[i];
    int4   d = dst4[i];
    float4 v = val4[i];
    int4   rk = ((const int4*)g_rank)[i];
    int op = (i * 4) / NNZ;
    int tag = op << 18;
    g_edge[g_seg[d.x * 16 + op] + rk.x] = make_int2(s.x | tag, __float_as_int(v.x));
    g_edge[g_seg[d.y * 16 + op] + rk.y] = make_int2(s.y | tag, __float_as_int(v.y));
    g_edge[g_seg[d.z * 16 + op] + rk.z] = make_int2(s.z | tag, __float_as_int(v.z));
    g_edge[g_seg[d.w * 16 + op] + rk.w] = make_int2(s.w | tag, __float_as_int(v.w));
}

// ---------------- sparse applies (steps 0,1): ballot-compacted ----------------
template<int STEP>
__global__ void apply_kernel(const int* __restrict__ queries) {
    constexpr bool IN_HALF     = (STEP >= 1);
    constexpr bool WRITE_FLAGS = (STEP < 1);

    __shared__ __align__(16) float4 sAttn4[RANKS * 13 * 32];
    __shared__ unsigned int sbits[NWORDS];
    __shared__ unsigned char sAny[16];

    const unsigned int* bitsIn  = (STEP == 1) ? g_bitsB : g_bitsA;

    int tid = threadIdx.x;
    for (int i = tid; i < NWORDS; i += 512) sbits[i] = bitsIn[i];
    float* sAttnF = (float*)sAttn4;
    for (int i = tid; i < RANKS * 13 * BATCH; i += 512) {
        int rk = i >> 7;
        int b  = i & 127;
        int r  = rk / 13, k = rk - r * 13;
        sAttnF[i] = g_attn24[((r * STEPS + STEP) * 13 + k) * NUM_EMB + queries[b]];
    }
    __syncthreads();

    int lane = tid & 31;
    int warp = tid >> 5;
    int j = blockIdx.x * 16 + warp;

    int rs = g_rowptr[j];
    int re = g_rowptr[j + 1];

    float4 acc[RANKS];
    #pragma unroll
    for (int r = 0; r < RANKS; r++) acc[r] = make_float4(0.f, 0.f, 0.f, 0.f);

    const uint2* memH = (const uint2*)g_memH1;
    unsigned int any = (sbits[j >> 4] >> (j & 15)) & 1u;
    if (any) {
        #pragma unroll
        for (int r = 0; r < RANKS; r++) {
            float4 a = sAttn4[(r * 13 + 12) * 32 + lane];
            float4 m;
            if constexpr (IN_HALF) {
                uint2 u = memH[(size_t)j * ROWH2 + r * 32 + lane];
                float2 f0 = __half22float2(*reinterpret_cast<__half2*>(&u.x));
                float2 f1 = __half22float2(*reinterpret_cast<__half2*>(&u.y));
                m = make_float4(f0.x, f0.y, f1.x, f1.y);
            } else {
                m = ((const float4*)g_memF)[(size_t)j * ROW4 + r * 32 + lane];
            }
            acc[r].x = a.x * m.x; acc[r].y = a.y * m.y;
            acc[r].z = a.z * m.z; acc[r].w = a.w * m.w;
        }
    }

    for (int e0 = rs; e0 < re; e0 += 32) {
        int e = e0 + lane;
        int meta = 0; float val = 0.f;
        bool act = false;
        if (e < re) {
            int2 ev = g_edge[e];
            meta = ev.x;
            val  = __int_as_float(ev.y);
            int s = meta & 0x3FFFF;
            act = (sbits[s >> 4] >> (s & 15)) & 1u;
        }
        unsigned int mask = __ballot_sync(0xffffffffu, act);
        any |= mask;
        while (mask) {
            int k = __ffs(mask) - 1;
            mask &= mask - 1;
            int   mk = __shfl_sync(0xffffffffu, meta, k);
            float vk = __shfl_sync(0xffffffffu, val,  k);
            int srck = mk & 0x3FFFF;
            int opk  = mk >> 18;
            if constexpr (IN_HALF) {
                const uint2* mrow = memH + (size_t)srck * ROWH2 + lane;
                uint2 u0 = mrow[0];
                uint2 u1 = mrow[32];
                uint2 u2 = mrow[64];
                const uint2 uu[3] = {u0, u1, u2};
                #pragma unroll
                for (int r = 0; r < RANKS; r++) {
                    float2 f0 = __half22float2(*reinterpret_cast<const __half2*>(&uu[r].x));
                    float2 f1 = __half22float2(*reinterpret_cast<const __half2*>(&uu[r].y));
                    float4 a = sAttn4[(r * 13 + opk) * 32 + lane];
                    acc[r].x = fmaf(vk * a.x, f0.x, acc[r].x);
                    acc[r].y = fmaf(vk * a.y, f0.y, acc[r].y);
                    acc[r].z = fmaf(vk * a.z, f1.x, acc[r].z);
                    acc[r].w = fmaf(vk * a.w, f1.y, acc[r].w);
                }
            } else {
                const float4* mrow = ((const float4*)g_memF) + (size_t)srck * ROW4 + lane;
                float4 m0 = mrow[0];
                float4 m1 = mrow[32];
                float4 m2 = mrow[64];
                const float4 mm[3] = {m0, m1, m2};
                #pragma unroll
                for (int r = 0; r < RANKS; r++) {
                    float4 a = sAttn4[(r * 13 + opk) * 32 + lane];
                    acc[r].x = fmaf(vk * a.x, mm[r].x, acc[r].x);
                    acc[r].y = fmaf(vk * a.y, mm[r].y, acc[r].y);
                    acc[r].z = fmaf(vk * a.z, mm[r].z, acc[r].z);
                    acc[r].w = fmaf(vk * a.w, mm[r].w, acc[r].w);
                }
            }
        }
    }

    {
        uint2* orow = ((uint2*)(STEP == 0 ? g_memH1 : g_memH2)) + (size_t)j * ROWH2;
        #pragma unroll
        for (int r = 0; r < RANKS; r++) {
            __half2 h0 = __floats2half2_rn(acc[r].x, acc[r].y);
            __half2 h1 = __floats2half2_rn(acc[r].z, acc[r].w);
            uint2 o;
            o.x = *reinterpret_cast<unsigned int*>(&h0);
            o.y = *reinterpret_cast<unsigned int*>(&h1);
            orow[r * 32 + lane] = o;
        }
    }

    if constexpr (WRITE_FLAGS) {
        if (lane == 0) sAny[warp] = (unsigned char)(any ? 1 : 0);
        __syncthreads();
        if (tid < 32) {
            unsigned int m = __ballot_sync(0xffffffffu, tid < 16 && sAny[tid]);
            if (tid == 0) g_bitsB[blockIdx.x] = m & 0xFFFFu;
        }
    }
}

// ---------------- dense apply t=2: op-segmented, two-level accumulation ----------------
__global__ void apply_dense_kernel(const int* __restrict__ queries) {
    __shared__ __align__(16) float4 sAttn4[RANKS * 13 * 32];

    int tid = threadIdx.x;
    float* sAttnF = (float*)sAttn4;
    for (int i = tid; i < RANKS * 13 * BATCH; i += 256) {
        int rk = i >> 7;
        int b  = i & 127;
        int r  = rk / 13, k = rk - r * 13;
        sAttnF[i] = g_attn24[((r * STEPS + 2) * 13 + k) * NUM_EMB + queries[b]];
    }
    __syncthreads();

    int lane = tid & 31;
    int warp = tid >> 5;
    int j = blockIdx.x * 8 + warp;

    float4 acc[RANKS];
    const uint2* memH = (const uint2*)g_memH2;

    {   // identity operator (k=12)
        #pragma unroll
        for (int r = 0; r < RANKS; r++) {
            float4 a = sAttn4[(r * 13 + 12) * 32 + lane];
            uint2 u = memH[(size_t)j * ROWH2 + r * 32 + lane];
            float2 f0 = __half22float2(*reinterpret_cast<__half2*>(&u.x));
            float2 f1 = __half22float2(*reinterpret_cast<__half2*>(&u.y));
            acc[r].x = a.x * f0.x; acc[r].y = a.y * f0.y;
            acc[r].z = a.z * f1.x; acc[r].w = a.w * f1.y;
        }
    }

    int segend = g_seg[j * 16 + 0];
    #pragma unroll
    for (int op = 0; op < NUM_OPS; op++) {
        int s = segend;
        segend = g_seg[j * 16 + op + 1];
        float4 T[RANKS];
        #pragma unroll
        for (int r = 0; r < RANKS; r++) T[r] = make_float4(0.f, 0.f, 0.f, 0.f);

        #pragma unroll 4
        for (int e = s; e < segend; e++) {
            int2 ev = g_edge[e];
            int   src = ev.x & 0x3FFFF;
            float vk  = __int_as_float(ev.y);
            const uint2* mrow = memH + (size_t)src * ROWH2 + lane;
            uint2 u0 = mrow[0];
            uint2 u1 = mrow[32];
            uint2 u2 = mrow[64];
            {
                float2 f0 = __half22float2(*reinterpret_cast<const __half2*>(&u0.x));
                float2 f1 = __half22float2(*reinterpret_cast<const __half2*>(&u0.y));
                T[0].x = fmaf(vk, f0.x, T[0].x);
                T[0].y = fmaf(vk, f0.y, T[0].y);
                T[0].z = fmaf(vk, f1.x, T[0].z);
                T[0].w = fmaf(vk, f1.y, T[0].w);
            }
            {
                float2 f0 = __half22float2(*reinterpret_cast<const __half2*>(&u1.x));
                float2 f1 = __half22float2(*reinterpret_cast<const __half2*>(&u1.y));
                T[1].x = fmaf(vk, f0.x, T[1].x);
                T[1].y = fmaf(vk, f0.y, T[1].y);
                T[1].z = fmaf(vk, f1.x, T[1].z);
                T[1].w = fmaf(vk, f1.y, T[1].w);
            }
            {
                float2 f0 = __half22float2(*reinterpret_cast<const __half2*>(&u2.x));
                float2 f1 = __half22float2(*reinterpret_cast<const __half2*>(&u2.y));
                T[2].x = fmaf(vk, f0.x, T[2].x);
                T[2].y = fmaf(vk, f0.y, T[2].y);
                T[2].z = fmaf(vk, f1.x, T[2].z);
                T[2].w = fmaf(vk, f1.y, T[2].w);
            }
        }

        #pragma unroll
        for (int r = 0; r < RANKS; r++) {
            float4 a = sAttn4[(r * 13 + op) * 32 + lane];
            acc[r].x = fmaf(a.x, T[r].x, acc[r].x);
            acc[r].y = fmaf(a.y, T[r].y, acc[r].y);
            acc[r].z = fmaf(a.z, T[r].z, acc[r].z);
            acc[r].w = fmaf(a.w, T[r].w, acc[r].w);
        }
    }

    float4* orow = ((float4*)g_memF) + (size_t)j * ROW4;
    #pragma unroll
    for (int r = 0; r < RANKS; r++) orow[r * 32 + lane] = acc[r];
}

// ---------------- normalize + fused output ----------------
__global__ void partial_kernel() {
    int tid = threadIdx.x;
    int j0  = blockIdx.x * (NUM_ENT / NPART);
    float s = 0.f;
    for (int k = 0; k < NUM_ENT / NPART; k++)
        s += g_memF[(size_t)(j0 + k) * ROWF + tid];
    g_part[blockIdx.x * ROWF + tid] = s;
}
__global__ void norm_kernel() {
    int tid = threadIdx.x;
    float s = 0.f;
    for (int k = 0; k < NPART; k++) s += g_part[k * ROWF + tid];
    g_inv[tid] = 1.f / fmaxf(1e-20f, s);
}
__global__ void final_kernel(float* __restrict__ out) {
    __shared__ float tile[32][33];
    __shared__ float sinv[RANKS][32];
    int j0 = blockIdx.x * 32, b0 = blockIdx.y * 32;
    int x = threadIdx.x, y = threadIdx.y;
    if (y < RANKS) sinv[y][x] = g_inv[y * BATCH + b0 + x];
    __syncthreads();
    const float* row = &g_memF[(size_t)(j0 + y) * ROWF + b0 + x];
    float v = row[0] * sinv[0][x] + row[BATCH] * sinv[1][x] + row[2 * BATCH] * sinv[2][x];
    tile[y][x] = v;
    __syncthreads();
    out[(size_t)(b0 + y) * NUM_ENT + (j0 + x)] = tile[x][y];
}

// ---------------- launch ----------------
extern "C" void kernel_launch(void* const* d_in, const int* in_sizes, int n_in,
                              void* d_out, int out_size) {
    const int*   queries  = (const int*)d_in[0];
    const int*   heads    = (const int*)d_in[1];
    const int*   edge_src = (const int*)d_in[2];
    const int*   edge_dst = (const int*)d_in[3];
    const float* edge_val = (const float*)d_in[4];
    const float* emb      = (const float*)d_in[5];
    const float* Wih_f    = (const float*)d_in[6];
    const float* Whh_f    = (const float*)d_in[7];
    const float* bih_f    = (const float*)d_in[8];
    const float* bhh_f    = (const float*)d_in[9];
    const float* Wih_b    = (const float*)d_in[10];
    const float* Whh_b    = (const float*)d_in[11];
    const float* bih_b    = (const float*)d_in[12];
    const float* bhh_b    = (const float*)d_in[13];
    const float* W0       = (const float*)d_in[14];
    const float* b0       = (const float*)d_in[15];
    float* out = (float*)d_out;
    (void)in_sizes; (void)n_in; (void)out_size;

    // K0: zero hist + flags + rowcnt pad
    k_zero<<<(NKEYS + 255) / 256, 256>>>();
    // K1: LSTM (first 144 blocks) overlapped with (dst,op)-histogram + rank capture
    k_hist_lstm<<<LSTM_BLOCKS + HIST_BLOCKS, 256>>>((const int4*)edge_dst, emb,
                                                    Wih_f, Whh_f, bih_f, bhh_f,
                                                    Wih_b, Whh_b, bih_b, bhh_b);
    // K2: attn (first 9 blocks) overlapped with parallel per-row totals
    k_rowsum_attn<<<ATTN_BLOCKS + RSUM_BLOCKS, 256>>>(W0, b0);
    // K3: shuffle scan over g_rowcnt
    k_scan<<<1, 1024>>>();
    // K4: per-(dst,op) segment offsets
    k_offsets<<<OFFS_BLOCKS, 384>>>();
    // fused init (zero head rows, then ones + flags; single block for ordering)
    k_init<<<1, ROWF>>>(heads);
    // K5: atomic-free scatter
    k_scatter<<<(ETOT / 4 + 255) / 256, 256>>>((const int4*)edge_src,
                                               (const int4*)edge_dst,
                                               (const float4*)edge_val);

    // applies: sparse (flags) -> sparse (flags) -> dense (op-segmented)
    apply_kernel<0><<<NUM_ENT / 16, 512>>>(queries);
    apply_kernel<1><<<NUM_ENT / 16, 512>>>(queries);
    apply_dense_kernel<<<NUM_ENT / 8, 256>>>(queries);

    // normalize per rank, sum ranks, transpose to (B, ENT)
    partial_kernel<<<NPART, ROWF>>>();
    norm_kernel<<<1, 1024 > ROWF ? ROWF : ROWF>>>();
    final_kernel<<<dim3(NUM_ENT / 32, BATCH / 32), dim3(32, 32)>>>(out);
}

// round 17
// speedup vs baseline: 1.1420x; 1.0445x over previous
#include <cuda_runtime.h>
#include <cuda_fp16.h>
#include <math.h>

#define NUM_ENT 40000
#define NUM_EMB 24
#define NUM_OPS 12
#define DIM     128
#define HID     128
#define BATCH   128
#define NNZ     300000
#define RANKS   3
#define STEPS   3
#define ETOT    (NUM_OPS * NNZ)
#define G4      (4 * HID)
#define ROWF    (RANKS * BATCH)     // 384 floats per entity row
#define ROW4    (ROWF / 4)
#define ROWH2   (ROWF / 4)          // 96 uint2 (fp16 rows)
#define NWORDS  (NUM_ENT / 16)
#define NPART   200
#define NKEYS   (NUM_ENT * 16)      // (dst,op) buckets, padded 12->16

// role split constants
#define LSTM_BLOCKS  (RANKS * 2 * NUM_EMB)          // 144
#define HIST_BLOCKS  ((ETOT / 4 + 255) / 256)       // 3516
#define ATTN_BLOCKS  (RANKS * STEPS)                // 9
#define RSUM_BLOCKS  ((NUM_ENT + 255) / 256)        // 157
#define OFFS_BLOCKS  ((NUM_ENT + 383) / 384)        // 105
#define SCAN_CH      40                              // rows per scan thread
#define RC_PAD       (1024 * SCAN_CH)                // 40960 (padded rowcnt)

// ---------------- scratch ----------------
__device__ float          g_memF[(size_t)NUM_ENT * ROWF];
__device__ uint2          g_memH1[(size_t)NUM_ENT * ROWH2];
__device__ uint2          g_memH2[(size_t)NUM_ENT * ROWH2];
__device__ int            g_hist12[NKEYS];
__device__ int            g_seg[NKEYS + 16];        // per-(dst,op) segment starts; [dst*16+12] = row end
__device__ int            g_rowcnt[RC_PAD];         // padded; tail zeroed
__device__ int            g_rowptr[NUM_ENT + 1];
__device__ int            g_chunkbase[1024];        // per-scan-thread exclusive bases
__device__ unsigned short g_rank16[ETOT];           // rank within (dst,op) bucket (max ~35)
__device__ int2           g_edge[ETOT];             // {src | op<<18, bits(val)}
__device__ unsigned int   g_bitsA[NWORDS];
__device__ unsigned int   g_bitsB[NWORDS];
__device__ float          g_hseq[RANKS * 2 * STEPS * NUM_EMB * HID];
__device__ float          g_attn24[RANKS * STEPS * 13 * NUM_EMB];
__device__ float          g_part[NPART * ROWF];
__device__ float          g_inv[ROWF];

__device__ __forceinline__ float warp_sum(float p) {
    p += __shfl_xor_sync(0xffffffffu, p, 16);
    p += __shfl_xor_sync(0xffffffffu, p, 8);
    p += __shfl_xor_sync(0xffffffffu, p, 4);
    p += __shfl_xor_sync(0xffffffffu, p, 2);
    p += __shfl_xor_sync(0xffffffffu, p, 1);
    return p;
}

// ---------------- K0: zero hist + flags + rowcnt pad ----------------
__global__ void k_zero() {
    int i = blockIdx.x * blockDim.x + threadIdx.x;
    if (i < NKEYS) g_hist12[i] = 0;
    if (i < NWORDS) g_bitsA[i] = 0;
    if (i < RC_PAD) g_rowcnt[i] = 0;
}

// ---------------- K1: LSTM (blocks 0..143) + histogram w/ rank capture ----------------
__global__ void k_hist_lstm(const int4* __restrict__ edge_dst4,
                            const float* __restrict__ emb,
                            const float* __restrict__ Wih_f, const float* __restrict__ Whh_f,
                            const float* __restrict__ bih_f, const float* __restrict__ bhh_f,
                            const float* __restrict__ Wih_b, const float* __restrict__ Whh_b,
                            const float* __restrict__ bih_b, const float* __restrict__ bhh_b)
{
    __shared__ __align__(16) float sq[DIM];
    __shared__ __align__(16) float sh[HID];
    __shared__ float sc[HID];
    __shared__ float sz[G4];
    __shared__ float sxw[G4];

    int tid = threadIdx.x;
    if (blockIdx.x >= LSTM_BLOCKS) {
        // ---- histogram role ----
        int i = (blockIdx.x - LSTM_BLOCKS) * 256 + tid;
        if (i < ETOT / 4) {
            int4 d = edge_dst4[i];
            int op = (i * 4) / NNZ;
            ushort4 rk;
            rk.x = (unsigned short)atomicAdd(&g_hist12[d.x * 16 + op], 1);
            rk.y = (unsigned short)atomicAdd(&g_hist12[d.y * 16 + op], 1);
            rk.z = (unsigned short)atomicAdd(&g_hist12[d.z * 16 + op], 1);
            rk.w = (unsigned short)atomicAdd(&g_hist12[d.w * 16 + op], 1);
            ((ushort4*)g_rank16)[i] = rk;
        }
        return;
    }

    // ---- LSTM role (blocks 0..143) ----
    int bb  = blockIdx.x % NUM_EMB;
    int dir = (blockIdx.x / NUM_EMB) % 2;
    int r   = blockIdx.x / (2 * NUM_EMB);
    const float* Wih = (dir ? Wih_b : Wih_f) + r * G4 * DIM;
    const float* Whh = (dir ? Whh_b : Whh_f) + r * G4 * HID;
    const float* bih = (dir ? bih_b : bih_f) + r * G4;
    const float* bhh = (dir ? bhh_b : bhh_f) + r * G4;

    int lane = tid & 31;
    int warp = tid >> 5;

    if (tid < DIM) {
        sq[tid] = emb[bb * DIM + tid];
        sh[tid] = 0.f;
        sc[tid] = 0.f;
    }
    __syncthreads();

    {
        float4 q4 = ((const float4*)sq)[lane];
        const float4* W4 = (const float4*)Wih;
        for (int o = 0; o < 64; o++) {
            int g = warp * 64 + o;
            float4 w = W4[g * 32 + lane];
            float p = w.x * q4.x + w.y * q4.y + w.z * q4.z + w.w * q4.w;
            p = warp_sum(p);
            if (lane == 0) sxw[g] = p + bih[g] + bhh[g];
        }
    }
    __syncthreads();

    for (int t = 0; t < STEPS; t++) {
        if (t == 0) {
            for (int g = tid; g < G4; g += 256) sz[g] = sxw[g];
        } else {
            float4 h4 = ((const float4*)sh)[lane];
            const float4* W4 = (const float4*)Whh;
            for (int o = 0; o < 64; o++) {
                int g = warp * 64 + o;
                float4 w = W4[g * 32 + lane];
                float p = w.x * h4.x + w.y * h4.y + w.z * h4.z + w.w * h4.w;
                p = warp_sum(p);
                if (lane == 0) sz[g] = sxw[g] + p;
            }
        }
        __syncthreads();
        if (tid < HID) {
            float zi = sz[tid], zf = sz[tid + HID], zg = sz[tid + 2 * HID], zo = sz[tid + 3 * HID];
            float ig = 1.f / (1.f + expf(-zi));
            float fg = 1.f / (1.f + expf(-zf));
            float gg = tanhf(zg);
            float og = 1.f / (1.f + expf(-zo));
            float c = fg * sc[tid] + ig * gg;
            float h = og * tanhf(c);
            sc[tid] = c;
            sh[tid] = h;
            g_hseq[(((r * 2 + dir) * STEPS + t) * NUM_EMB + bb) * HID + tid] = h;
        }
        __syncthreads();
    }
}

// ---------------- K2: attn (0..8) + parallel rowsum (9..9+156) + init (last block) ----------------
__global__ void k_rowsum_attn(const float* __restrict__ W0, const float* __restrict__ b0p,
                              const int* __restrict__ heads) {
    __shared__ float sW[256 * 13];
    __shared__ int srow[BATCH];
    int tid = threadIdx.x;

    if (blockIdx.x == ATTN_BLOCKS + RSUM_BLOCKS) {
        // ---- init role: zero head rows, then set ones + flag bits (ordered in-block) ----
        if (tid < BATCH) srow[tid] = heads[tid];
        __syncthreads();
        for (int b = 0; b < BATCH; b++)
            for (int idx = tid; idx < ROWF; idx += 256)
                g_memF[(size_t)srow[b] * ROWF + idx] = 0.f;
        __syncthreads();
        if (tid < BATCH) {
            int row = srow[tid];
            #pragma unroll
            for (int r = 0; r < RANKS; r++)
                g_memF[(size_t)row * ROWF + r * BATCH + tid] = 1.f;
            atomicOr(&g_bitsA[row >> 4], 1u << (row & 15));
        }
        return;
    }
    if (blockIdx.x >= ATTN_BLOCKS) {
        // ---- rowsum role ----
        int dst = (blockIdx.x - ATTN_BLOCKS) * 256 + tid;
        if (dst < NUM_ENT) {
            const int4* h4 = (const int4*)&g_hist12[dst * 16];
            int4 a = h4[0], b = h4[1], c = h4[2];
            g_rowcnt[dst] = a.x + a.y + a.z + a.w + b.x + b.y + b.z + b.w + c.x + c.y + c.z + c.w;
        }
        return;
    }
    // ---- attn role ----
    int r = blockIdx.x / STEPS;
    int t = blockIdx.x % STEPS;
    for (int i = tid; i < 256 * 13; i += 256) sW[i] = W0[i];
    __syncthreads();
    if (tid >= NUM_EMB) return;
    int q = tid;
    const float* hf = &g_hseq[(((r * 2 + 0) * STEPS + t) * NUM_EMB + q) * HID];
    const float* hb = &g_hseq[(((r * 2 + 1) * STEPS + (STEPS - 1 - t)) * NUM_EMB + q) * HID];
    float l[13];
    #pragma unroll
    for (int k = 0; k < 13; k++) l[k] = b0p[k];
    for (int d = 0; d < HID; d++) {
        float hv = hf[d];
        #pragma unroll
        for (int k = 0; k < 13; k++) l[k] += hv * sW[d * 13 + k];
    }
    for (int d = 0; d < HID; d++) {
        float hv = hb[d];
        #pragma unroll
        for (int k = 0; k < 13; k++) l[k] += hv * sW[(HID + d) * 13 + k];
    }
    float m = l[0];
    #pragma unroll
    for (int k = 1; k < 13; k++) m = fmaxf(m, l[k]);
    float s = 0.f;
    #pragma unroll
    for (int k = 0; k < 13; k++) { l[k] = expf(l[k] - m); s += l[k]; }
    float inv = 1.f / s;
    #pragma unroll
    for (int k = 0; k < 13; k++)
        g_attn24[((r * STEPS + t) * 13 + k) * NUM_EMB + q] = l[k] * inv;
}

// ---------------- K3: chunk-base scan (1 block, 1024 threads; writes only 1024 bases) ----------------
__global__ void k_scan() {
    __shared__ int swarp[32];
    int tid  = threadIdx.x;
    int lane = tid & 31;
    int warp = tid >> 5;

    const int4* rc4 = (const int4*)&g_rowcnt[tid * SCAN_CH];
    int s = 0;
    #pragma unroll
    for (int k = 0; k < SCAN_CH / 4; k++) {        // 10 independent int4 loads
        int4 c4 = rc4[k];
        s += c4.x + c4.y + c4.z + c4.w;
    }

    int inc = s;
    #pragma unroll
    for (int d = 1; d < 32; d <<= 1) {
        int n = __shfl_up_sync(0xffffffffu, inc, d);
        if (lane >= d) inc += n;
    }
    if (lane == 31) swarp[warp] = inc;
    __syncthreads();
    if (warp == 0) {
        int v = swarp[lane];
        #pragma unroll
        for (int d = 1; d < 32; d <<= 1) {
            int n = __shfl_up_sync(0xffffffffu, v, d);
            if (lane >= d) v += n;
        }
        swarp[lane] = v;
    }
    __syncthreads();

    g_chunkbase[tid] = (inc - s) + (warp ? swarp[warp - 1] : 0);   // exclusive prefix
}

// ---------------- K4: rowptr + per-(dst,op) segment offsets (parallel) ----------------
__global__ void k_offsets(void) {
    int dst = blockIdx.x * 384 + threadIdx.x;
    if (dst >= NUM_ENT) return;
    int chunk = dst / SCAN_CH;
    int base = g_chunkbase[chunk];
    for (int i = chunk * SCAN_CH; i < dst; i++) base += g_rowcnt[i];   // L1-hot, <=39 adds
    g_rowptr[dst] = base;
    int run = base;
    #pragma unroll
    for (int op = 0; op < NUM_OPS; op++) {
        g_seg[dst * 16 + op] = run;
        run += g_hist12[dst * 16 + op];
    }
    g_seg[dst * 16 + 12] = run;
    if (dst == NUM_ENT - 1) g_rowptr[NUM_ENT] = run;
}

// ---------------- K5: scatter (atomic-free, 16-bit ranks) ----------------
__global__ void k_scatter(const int4* __restrict__ src4,
                          const int4* __restrict__ dst4,
                          const float4* __restrict__ val4) {
    int i = blockIdx.x * blockDim.x + threadIdx.x;
    if (i >= ETOT / 4) return;
    int4    s  = src4[i];
    int4    d  = dst4[i];
    float4  v  = val4[i];
    ushort4 rk = ((const ushort4*)g_rank16)[i];
    int op = (i * 4) / NNZ;
    int tag = op << 18;
    g_edge[g_seg[d.x * 16 + op] + rk.x] = make_int2(s.x | tag, __float_as_int(v.x));
    g_edge[g_seg[d.y * 16 + op] + rk.y] = make_int2(s.y | tag, __float_as_int(v.y));
    g_edge[g_seg[d.z * 16 + op] + rk.z] = make_int2(s.z | tag, __float_as_int(v.z));
    g_edge[g_seg[d.w * 16 + op] + rk.w] = make_int2(s.w | tag, __float_as_int(v.w));
}

// ---------------- sparse applies (steps 0,1): ballot-compacted ----------------
template<int STEP>
__global__ void apply_kernel(const int* __restrict__ queries) {
    constexpr bool IN_HALF     = (STEP >= 1);
    constexpr bool WRITE_FLAGS = (STEP < 1);

    __shared__ __align__(16) float4 sAttn4[RANKS * 13 * 32];
    __shared__ unsigned int sbits[NWORDS];
    __shared__ unsigned char sAny[16];

    const unsigned int* bitsIn  = (STEP == 1) ? g_bitsB : g_bitsA;

    int tid = threadIdx.x;
    for (int i = tid; i < NWORDS; i += 512) sbits[i] = bitsIn[i];
    float* sAttnF = (float*)sAttn4;
    for (int i = tid; i < RANKS * 13 * BATCH; i += 512) {
        int rk = i >> 7;
        int b  = i & 127;
        int r  = rk / 13, k = rk - r * 13;
        sAttnF[i] = g_attn24[((r * STEPS + STEP) * 13 + k) * NUM_EMB + queries[b]];
    }
    __syncthreads();

    int lane = tid & 31;
    int warp = tid >> 5;
    int j = blockIdx.x * 16 + warp;

    int rs = g_rowptr[j];
    int re = g_rowptr[j + 1];

    float4 acc[RANKS];
    #pragma unroll
    for (int r = 0; r < RANKS; r++) acc[r] = make_float4(0.f, 0.f, 0.f, 0.f);

    const uint2* memH = (const uint2*)g_memH1;
    unsigned int any = (sbits[j >> 4] >> (j & 15)) & 1u;
    if (any) {
        #pragma unroll
        for (int r = 0; r < RANKS; r++) {
            float4 a = sAttn4[(r * 13 + 12) * 32 + lane];
            float4 m;
            if constexpr (IN_HALF) {
                uint2 u = memH[(size_t)j * ROWH2 + r * 32 + lane];
                float2 f0 = __half22float2(*reinterpret_cast<__half2*>(&u.x));
                float2 f1 = __half22float2(*reinterpret_cast<__half2*>(&u.y));
                m = make_float4(f0.x, f0.y, f1.x, f1.y);
            } else {
                m = ((const float4*)g_memF)[(size_t)j * ROW4 + r * 32 + lane];
            }
            acc[r].x = a.x * m.x; acc[r].y = a.y * m.y;
            acc[r].z = a.z * m.z; acc[r].w = a.w * m.w;
        }
    }

    for (int e0 = rs; e0 < re; e0 += 32) {
        int e = e0 + lane;
        int meta = 0; float val = 0.f;
        bool act = false;
        if (e < re) {
            int2 ev = g_edge[e];
            meta = ev.x;
            val  = __int_as_float(ev.y);
            int s = meta & 0x3FFFF;
            act = (sbits[s >> 4] >> (s & 15)) & 1u;
        }
        unsigned int mask = __ballot_sync(0xffffffffu, act);
        any |= mask;
        while (mask) {
            int k = __ffs(mask) - 1;
            mask &= mask - 1;
            int   mk = __shfl_sync(0xffffffffu, meta, k);
            float vk = __shfl_sync(0xffffffffu, val,  k);
            int srck = mk & 0x3FFFF;
            int opk  = mk >> 18;
            if constexpr (IN_HALF) {
                const uint2* mrow = memH + (size_t)srck * ROWH2 + lane;
                uint2 u0 = mrow[0];
                uint2 u1 = mrow[32];
                uint2 u2 = mrow[64];
                const uint2 uu[3] = {u0, u1, u2};
                #pragma unroll
                for (int r = 0; r < RANKS; r++) {
                    float2 f0 = __half22float2(*reinterpret_cast<const __half2*>(&uu[r].x));
                    float2 f1 = __half22float2(*reinterpret_cast<const __half2*>(&uu[r].y));
                    float4 a = sAttn4[(r * 13 + opk) * 32 + lane];
                    acc[r].x = fmaf(vk * a.x, f0.x, acc[r].x);
                    acc[r].y = fmaf(vk * a.y, f0.y, acc[r].y);
                    acc[r].z = fmaf(vk * a.z, f1.x, acc[r].z);
                    acc[r].w = fmaf(vk * a.w, f1.y, acc[r].w);
                }
            } else {
                const float4* mrow = ((const float4*)g_memF) + (size_t)srck * ROW4 + lane;
                float4 m0 = mrow[0];
                float4 m1 = mrow[32];
                float4 m2 = mrow[64];
                const float4 mm[3] = {m0, m1, m2};
                #pragma unroll
                for (int r = 0; r < RANKS; r++) {
                    float4 a = sAttn4[(r * 13 + opk) * 32 + lane];
                    acc[r].x = fmaf(vk * a.x, mm[r].x, acc[r].x);
                    acc[r].y = fmaf(vk * a.y, mm[r].y, acc[r].y);
                    acc[r].z = fmaf(vk * a.z, mm[r].z, acc[r].z);
                    acc[r].w = fmaf(vk * a.w, mm[r].w, acc[r].w);
                }
            }
        }
    }

    {
        uint2* orow = ((uint2*)(STEP == 0 ? g_memH1 : g_memH2)) + (size_t)j * ROWH2;
        #pragma unroll
        for (int r = 0; r < RANKS; r++) {
            __half2 h0 = __floats2half2_rn(acc[r].x, acc[r].y);
            __half2 h1 = __floats2half2_rn(acc[r].z, acc[r].w);
            uint2 o;
            o.x = *reinterpret_cast<unsigned int*>(&h0);
            o.y = *reinterpret_cast<unsigned int*>(&h1);
            orow[r * 32 + lane] = o;
        }
    }

    if constexpr (WRITE_FLAGS) {
        if (lane == 0) sAny[warp] = (unsigned char)(any ? 1 : 0);
        __syncthreads();
        if (tid < 32) {
            unsigned int m = __ballot_sync(0xffffffffu, tid < 16 && sAny[tid]);
            if (tid == 0) g_bitsB[blockIdx.x] = m & 0xFFFFu;
        }
    }
}

// ---------------- dense apply t=2: op-segmented, two-level accumulation ----------------
__global__ void apply_dense_kernel(const int* __restrict__ queries) {
    __shared__ __align__(16) float4 sAttn4[RANKS * 13 * 32];

    int tid = threadIdx.x;
    float* sAttnF = (float*)sAttn4;
    for (int i = tid; i < RANKS * 13 * BATCH; i += 256) {
        int rk = i >> 7;
        int b  = i & 127;
        int r  = rk / 13, k = rk - r * 13;
        sAttnF[i] = g_attn24[((r * STEPS + 2) * 13 + k) * NUM_EMB + queries[b]];
    }
    __syncthreads();

    int lane = tid & 31;
    int warp = tid >> 5;
    int j = blockIdx.x * 8 + warp;

    float4 acc[RANKS];
    const uint2* memH = (const uint2*)g_memH2;

    {   // identity operator (k=12)
        #pragma unroll
        for (int r = 0; r < RANKS; r++) {
            float4 a = sAttn4[(r * 13 + 12) * 32 + lane];
            uint2 u = memH[(size_t)j * ROWH2 + r * 32 + lane];
            float2 f0 = __half22float2(*reinterpret_cast<__half2*>(&u.x));
            float2 f1 = __half22float2(*reinterpret_cast<__half2*>(&u.y));
            acc[r].x = a.x * f0.x; acc[r].y = a.y * f0.y;
            acc[r].z = a.z * f1.x; acc[r].w = a.w * f1.y;
        }
    }

    int segend = g_seg[j * 16 + 0];
    #pragma unroll
    for (int op = 0; op < NUM_OPS; op++) {
        int s = segend;
        segend = g_seg[j * 16 + op + 1];
        float4 T[RANKS];
        #pragma unroll
        for (int r = 0; r < RANKS; r++) T[r] = make_float4(0.f, 0.f, 0.f, 0.f);

        #pragma unroll 4
        for (int e = s; e < segend; e++) {
            int2 ev = g_edge[e];
            int   src = ev.x & 0x3FFFF;
            float vk  = __int_as_float(ev.y);
            const uint2* mrow = memH + (size_t)src * ROWH2 + lane;
            uint2 u0 = mrow[0];
            uint2 u1 = mrow[32];
            uint2 u2 = mrow[64];
            {
                float2 f0 = __half22float2(*reinterpret_cast<const __half2*>(&u0.x));
                float2 f1 = __half22float2(*reinterpret_cast<const __half2*>(&u0.y));
                T[0].x = fmaf(vk, f0.x, T[0].x);
                T[0].y = fmaf(vk, f0.y, T[0].y);
                T[0].z = fmaf(vk, f1.x, T[0].z);
                T[0].w = fmaf(vk, f1.y, T[0].w);
            }
            {
                float2 f0 = __half22float2(*reinterpret_cast<const __half2*>(&u1.x));
                float2 f1 = __half22float2(*reinterpret_cast<const __half2*>(&u1.y));
                T[1].x = fmaf(vk, f0.x, T[1].x);
                T[1].y = fmaf(vk, f0.y, T[1].y);
                T[1].z = fmaf(vk, f1.x, T[1].z);
                T[1].w = fmaf(vk, f1.y, T[1].w);
            }
            {
                float2 f0 = __half22float2(*reinterpret_cast<const __half2*>(&u2.x));
                float2 f1 = __half22float2(*reinterpret_cast<const __half2*>(&u2.y));
                T[2].x = fmaf(vk, f0.x, T[2].x);
                T[2].y = fmaf(vk, f0.y, T[2].y);
                T[2].z = fmaf(vk, f1.x, T[2].z);
                T[2].w = fmaf(vk, f1.y, T[2].w);
            }
        }

        #pragma unroll
        for (int r = 0; r < RANKS; r++) {
            float4 a = sAttn4[(r * 13 + op) * 32 + lane];
            acc[r].x = fmaf(a.x, T[r].x, acc[r].x);
            acc[r].y = fmaf(a.y, T[r].y, acc[r].y);
            acc[r].z = fmaf(a.z, T[r].z, acc[r].z);
            acc[r].w = fmaf(a.w, T[r].w, acc[r].w);
        }
    }

    float4* orow = ((float4*)g_memF) + (size_t)j * ROW4;
    #pragma unroll
    for (int r = 0; r < RANKS; r++) orow[r * 32 + lane] = acc[r];
}

// ---------------- normalize + fused output ----------------
__global__ void partial_kernel() {
    int tid = threadIdx.x;
    int j0  = blockIdx.x * (NUM_ENT / NPART);
    float s = 0.f;
    for (int k = 0; k < NUM_ENT / NPART; k++)
        s += g_memF[(size_t)(j0 + k) * ROWF + tid];
    g_part[blockIdx.x * ROWF + tid] = s;
}
__global__ void norm_kernel() {
    int tid = threadIdx.x;
    float s = 0.f;
    for (int k = 0; k < NPART; k++) s += g_part[k * ROWF + tid];
    g_inv[tid] = 1.f / fmaxf(1e-20f, s);
}
__global__ void final_kernel(float* __restrict__ out) {
    __shared__ float tile[32][33];
    __shared__ float sinv[RANKS][32];
    int j0 = blockIdx.x * 32, b0 = blockIdx.y * 32;
    int x = threadIdx.x, y = threadIdx.y;
    if (y < RANKS) sinv[y][x] = g_inv[y * BATCH + b0 + x];
    __syncthreads();
    const float* row = &g_memF[(size_t)(j0 + y) * ROWF + b0 + x];
    float v = row[0] * sinv[0][x] + row[BATCH] * sinv[1][x] + row[2 * BATCH] * sinv[2][x];
    tile[y][x] = v;
    __syncthreads();
    out[(size_t)(b0 + y) * NUM_ENT + (j0 + x)] = tile[x][y];
}

// ---------------- launch ----------------
extern "C" void kernel_launch(void* const* d_in, const int* in_sizes, int n_in,
                              void* d_out, int out_size) {
    const int*   queries  = (const int*)d_in[0];
    const int*   heads    = (const int*)d_in[1];
    const int*   edge_src = (const int*)d_in[2];
    const int*   edge_dst = (const int*)d_in[3];
    const float* edge_val = (const float*)d_in[4];
    const float* emb      = (const float*)d_in[5];
    const float* Wih_f    = (const float*)d_in[6];
    const float* Whh_f    = (const float*)d_in[7];
    const float* bih_f    = (const float*)d_in[8];
    const float* bhh_f    = (const float*)d_in[9];
    const float* Wih_b    = (const float*)d_in[10];
    const float* Whh_b    = (const float*)d_in[11];
    const float* bih_b    = (const float*)d_in[12];
    const float* bhh_b    = (const float*)d_in[13];
    const float* W0       = (const float*)d_in[14];
    const float* b0       = (const float*)d_in[15];
    float* out = (float*)d_out;
    (void)in_sizes; (void)n_in; (void)out_size;

    // K0: zero hist + flags + rowcnt pad
    k_zero<<<(NKEYS + 255) / 256, 256>>>();
    // K1: LSTM (first 144 blocks) overlapped with (dst,op)-histogram + 16-bit rank capture
    k_hist_lstm<<<LSTM_BLOCKS + HIST_BLOCKS, 256>>>((const int4*)edge_dst, emb,
                                                    Wih_f, Whh_f, bih_f, bhh_f,
                                                    Wih_b, Whh_b, bih_b, bhh_b);
    // K2: attn + parallel rowsum + head-row init (block roles)
    k_rowsum_attn<<<ATTN_BLOCKS + RSUM_BLOCKS + 1, 256>>>(W0, b0, heads);
    // K3: chunk-base scan (1024 bases only)
    k_scan<<<1, 1024>>>();
    // K4: rowptr + per-(dst,op) segment offsets (parallel)
    k_offsets<<<OFFS_BLOCKS, 384>>>();
    // K5: atomic-free scatter
    k_scatter<<<(ETOT / 4 + 255) / 256, 256>>>((const int4*)edge_src,
                                               (const int4*)edge_dst,
                                               (const float4*)edge_val);

    // applies: sparse (flags) -> sparse (flags) -> dense (op-segmented)
    apply_kernel<0><<<NUM_ENT / 16, 512>>>(queries);
    apply_kernel<1><<<NUM_ENT / 16, 512>>>(queries);
    apply_dense_kernel<<<NUM_ENT / 8, 256>>>(queries);

    // normalize per rank, sum ranks, transpose to (B, ENT)
    partial_kernel<<<NPART, ROWF>>>();
    norm_kernel<<<1, ROWF>>>();
    final_kernel<<<dim3(NUM_ENT / 32, BATCH / 32), dim3(32, 32)>>>(out);
}